// round 9
// baseline (speedup 1.0000x reference)
#include <cuda_runtime.h>

// Fixed problem shapes: B=4, L=80000, N=512, F=257, STRIDE=256 -> T=311
#define NB  4
#define NL  80000
#define NN  512
#define NF  257
#define NT  311
#define BFT (NB * NF * NT)   // 319708

#define TWO_PI 6.2831853071795864769f

__device__ __forceinline__ int bitrev4c(int v) {   // compile-time use
    return ((v & 1) << 3) | ((v & 2) << 1) | ((v & 4) >> 1) | ((v & 8) >> 3);
}

// ---------------------------------------------------------------------------
// One WARP per (frame t, batch b). blockDim 128 (warp w = batch w), grid NT.
// Lane l holds points n = 32k + l for k = 0..15 in registers (complex z[k]).
//  Local stages H=256,128,64,32: register-pair DIF butterflies (k, k+H/32),
//    twiddle angle -2*pi*(32*(k mod (H/32)) + l)/(2H). No communication.
//  Shfl stages H=16..1: lane-pair butterflies on each register (sub-block
//    r = k, position m = l), identical math to the verified round-8 code.
//  Emit: f = 16*bitrev5(l) + bitrev4(k). Even lanes emit 16 freqs, lane 1
//    emits f=256 from k=0. No smem, no barriers.
// Output layout: floats [0,BFT) = spec; [BFT,2*BFT) = real(stft).
// ---------------------------------------------------------------------------
__global__ void __launch_bounds__(128, 4)
adstft_kernel(const float* __restrict__ x,
              const float* __restrict__ wlp,
              const float* __restrict__ stp,
              float* __restrict__ out) {
    const int t = blockIdx.x;
    const int b = threadIdx.x >> 5;
    const int l = threadIdx.x & 31;

    const float wl = fminf(fmaxf(wlp[0], 25.6f), 512.0f);   // WIN_MIN..WIN_MAX
    const float st = fminf(fmaxf(stp[0], 0.0f), 512.0f);    // STRIDE_MIN..MAX
    const float frame = st * (float)t;                       // == cumsum for integral st
    const float flo   = floorf(frame);
    const float frac  = frame - flo;
    const int   i0    = (int)flo;
    const float hi    = ceilf ((511.0f + wl) * 0.5f);
    const float lo    = floorf((511.0f - wl) * 0.5f);
    const float woff  = (wl - 511.0f) * 0.5f;

    // ---- Load + window: z[k] = x[i0 + 32k + l] * tap(32k + l) ----
    float zr[16], zi[16];
    {
        const float* xb = x + (size_t)b * NL;
#pragma unroll
        for (int k = 0; k < 16; ++k) {
            const int n   = 32 * k + l;
            const int idx = i0 + n;
            const float v = (idx >= 0 && idx < NL) ? xb[idx] : 0.0f;
            const float base = (float)n - frac;
            float tap = 0.0f;
            if (!(base >= hi || base <= lo))
                tap = (0.5f - 0.5f * __cosf(TWO_PI * (base + woff) / wl))
                      * 0.00390625f;                         // / N * 2
            zr[k] = v * tap;
            zi[k] = 0.0f;
        }
    }

    // ---- Local register stages: H = 256, 128, 64, 32  (Hk = H/32) ----
#pragma unroll
    for (int s = 0; s < 4; ++s) {
        const int Hk = 8 >> s;
#pragma unroll
        for (int jk = 0; jk < 8; ++jk) {
            if (jk >= Hk) break;
            float sn, c;
            __sincosf(-TWO_PI * (float)(32 * jk + l) / (float)(64 * Hk),
                      &sn, &c);
#pragma unroll
            for (int blk = 0; blk < 8; ++blk) {
                if (blk >= 8 / Hk) break;
                const int k0 = blk * 2 * Hk + jk;
                const int k1 = k0 + Hk;
                const float dr = zr[k0] - zr[k1];
                const float di = zi[k0] - zi[k1];
                zr[k0] += zr[k1];
                zi[k0] += zi[k1];
                zr[k1] = fmaf(dr, c,  -di * sn);
                zi[k1] = fmaf(dr, sn,  di * c);
            }
        }
    }

    // ---- Shfl stages: H = 16, 8, 4, 2, 1 on each register ----
#pragma unroll
    for (int h = 16; h >= 1; h >>= 1) {
        const int step = 16 / h;
        float twn, twc;
        __sincosf(-TWO_PI * (float)(step * (l & (h - 1))) * (1.0f / 32.0f),
                  &twn, &twc);
        const bool bot = (l & h) != 0;
#pragma unroll
        for (int k = 0; k < 16; ++k) {
            const float pr = __shfl_xor_sync(0xffffffffu, zr[k], h);
            const float pi = __shfl_xor_sync(0xffffffffu, zi[k], h);
            const float dr = pr - zr[k];
            const float di = pi - zi[k];
            const float tr = fmaf(dr, twc, -di * twn);
            const float ti = fmaf(dr, twn,  di * twc);
            zr[k] = bot ? tr : (zr[k] + pr);
            zi[k] = bot ? ti : (zi[k] + pi);
        }
    }

    // ---- Emit: f = 16*bitrev5(l) + bitrev4(k) ----
    const int q5 = ((l & 1) << 4) | ((l & 2) << 2) | (l & 4)
                 | ((l & 8) >> 2) | ((l & 16) >> 4);          // bitrev5(l)

    if ((l & 1) == 0) {                                       // q5 <= 15
        const int fbase = q5 << 4;
#pragma unroll
        for (int k = 0; k < 16; ++k) {
            const int f = fbase | bitrev4c(k);
            float sp, cp;
            __sincosf(TWO_PI * frac * (float)f * (1.0f / 512.0f), &sp, &cp);
            const float re = fmaf(zr[k], cp, -zi[k] * sp);
            const float im = fmaf(zr[k], sp,  zi[k] * cp);
            const size_t o = ((size_t)b * NF + f) * NT + t;
            out[o]       = sqrtf(fmaf(re, re, im * im)) + 1.1920929e-7f;
            out[BFT + o] = re;
        }
    } else if (l == 1) {                                      // q5 == 16 -> f = 256
        float sp, cp;
        __sincosf(TWO_PI * frac * 0.5f, &sp, &cp);            // f=256: 2pi*frac/2
        const float re = fmaf(zr[0], cp, -zi[0] * sp);
        const float im = fmaf(zr[0], sp,  zi[0] * cp);
        const size_t o = ((size_t)b * NF + 256) * NT + t;
        out[o]       = sqrtf(fmaf(re, re, im * im)) + 1.1920929e-7f;
        out[BFT + o] = re;
    }
}

// ---------------------------------------------------------------------------
extern "C" void kernel_launch(void* const* d_in, const int* in_sizes, int n_in,
                              void* d_out, int out_size) {
    // x is the unique large input; win_length is the middle input under both
    // insertion and alphabetical order; strides is the remaining small one.
    int ix = 0;
    for (int i = 1; i < n_in; ++i)
        if (in_sizes[i] > in_sizes[ix]) ix = i;
    const float* x  = (const float*)d_in[ix];
    const float* wl = (const float*)d_in[1];
    const float* st = (const float*)d_in[(ix == 0) ? 2 : 0];
    float* out = (float*)d_out;

    adstft_kernel<<<NT, 128>>>(x, wl, st, out);
}

// round 10
// speedup vs baseline: 1.2113x; 1.2113x over previous
#include <cuda_runtime.h>

// Fixed problem shapes: B=4, L=80000, N=512, F=257, STRIDE=256 -> T=311
#define NB  4
#define NL  80000
#define NN  512
#define NF  257
#define NT  311
#define BFT (NB * NF * NT)   // 319708

#define TWO_PI 6.2831853071795864769f

// ---------------------------------------------------------------------------
// Block = 128 threads (4 warps) per (frame t, batch b); grid (NT, NB).
// Lane l of warp m owns registers k=0..3 holding point n = 32*(4m+k) + l.
//  Cross-warp stages H=256 & H=128 (kk-distance 8, 4): fused radix-4
//    exchange via smem, ONE barrier. Thread at quartet position q=m computes
//      B0 = s0+s1, B1 = (s0-s1)*wB, B2 = wA*(d0 - i*d1), B3 = wA*wB*(d0 + i*d1)
//    with s=c0±c2 sums, d=c0-c2 / c1-c3, wA = w(l)*e^{-i*pi*k/8}, wB = wA^2.
//  Stages H=64, 32: register-local DIF butterflies.
//  Stages H=16..1: shfl-xor butterflies (verified rounds 8-9).
//  Emit: f = 16*bitrev5(l) + bitrev4(kk); even lanes emit 4 freqs,
//        warp 0 lane 1 emits f=256.
// Output layout: floats [0,BFT) = spec; [BFT,2*BFT) = real(stft).
// ---------------------------------------------------------------------------
__global__ void __launch_bounds__(128, 8)
adstft_kernel(const float* __restrict__ x,
              const float* __restrict__ wlp,
              const float* __restrict__ stp,
              float* __restrict__ out) {
    __shared__ float2 sz[16][32];   // [kk][lane], 4 KB

    const int t = blockIdx.x;
    const int b = blockIdx.y;
    const int m = threadIdx.x >> 5;   // warp = quartet position q
    const int l = threadIdx.x & 31;

    const float wl = fminf(fmaxf(wlp[0], 25.6f), 512.0f);   // WIN_MIN..WIN_MAX
    const float st = fminf(fmaxf(stp[0], 0.0f), 512.0f);    // STRIDE_MIN..MAX
    const float frame = st * (float)t;                       // == cumsum for integral st
    const float flo   = floorf(frame);
    const float frac  = frame - flo;
    const int   i0    = (int)flo;
    const float hi    = ceilf ((511.0f + wl) * 0.5f);
    const float lo    = floorf((511.0f - wl) * 0.5f);
    const float woff  = (wl - 511.0f) * 0.5f;

    // ---- Load + window, write to smem ----
    {
        const float* xb = x + (size_t)b * NL;
#pragma unroll
        for (int k = 0; k < 4; ++k) {
            const int n   = 32 * (4 * m + k) + l;
            const int idx = i0 + n;
            const float v = (idx >= 0 && idx < NL) ? xb[idx] : 0.0f;
            const float base = (float)n - frac;
            float tap = 0.0f;
            if (!(base >= hi || base <= lo))
                tap = (0.5f - 0.5f * __cosf(TWO_PI * (base + woff) / wl))
                      * 0.00390625f;                         // / N * 2
            sz[4 * m + k][l] = make_float2(v * tap, 0.0f);
        }
    }
    __syncthreads();

    // ---- Fused radix-4 cross-warp stages (H=256 then H=128) ----
    float zr[4], zi[4];
    {
        float wlr, wli;                               // w(l) = e^{-2*pi*i*l/512}
        __sincosf(-TWO_PI * (float)l * (1.0f / 512.0f), &wli, &wlr);
        const float KC[4] = {1.0f, 0.92387953f,  0.70710678f,  0.38268343f};
        const float KS[4] = {0.0f, -0.38268343f, -0.70710678f, -0.92387953f};
#pragma unroll
        for (int k = 0; k < 4; ++k) {
            // wA = w(l) * e^{-i*pi*k/8};  wB = wA^2
            const float wAr = wlr * KC[k] - wli * KS[k];
            const float wAi = wlr * KS[k] + wli * KC[k];
            const float wBr = wAr * wAr - wAi * wAi;
            const float wBi = 2.0f * wAr * wAi;

            const float2 c0 = sz[k     ][l];
            const float2 c1 = sz[k +  4][l];
            const float2 c2 = sz[k +  8][l];
            const float2 c3 = sz[k + 12][l];
            const float s0r = c0.x + c2.x, s0i = c0.y + c2.y;
            const float s1r = c1.x + c3.x, s1i = c1.y + c3.y;
            const float d0r = c0.x - c2.x, d0i = c0.y - c2.y;
            const float d1r = c1.x - c3.x, d1i = c1.y - c3.y;

            float rr, ri;
            if (m == 0) {                       // B0 = s0 + s1
                rr = s0r + s1r; ri = s0i + s1i;
            } else if (m == 1) {                // B1 = (s0 - s1) * wB
                const float er = s0r - s1r, ei = s0i - s1i;
                rr = er * wBr - ei * wBi;
                ri = er * wBi + ei * wBr;
            } else if (m == 2) {                // B2 = wA * (d0 - i*d1)
                const float er = d0r + d1i, ei = d0i - d1r;
                rr = er * wAr - ei * wAi;
                ri = er * wAi + ei * wAr;
            } else {                            // B3 = wA*wB * (d0 + i*d1)
                const float wCr = wAr * wBr - wAi * wBi;
                const float wCi = wAr * wBi + wAi * wBr;
                const float er = d0r - d1i, ei = d0i + d1r;
                rr = er * wCr - ei * wCi;
                ri = er * wCi + ei * wCr;
            }
            zr[k] = rr; zi[k] = ri;
        }
    }

    // ---- Register-local stages H=64 (dist 2), H=32 (dist 1) ----
    {
        // H=64: pairs (k, k+2), jk = k, angle = -2*pi*(32k + l)/128
#pragma unroll
        for (int k = 0; k < 2; ++k) {
            float sn, c;
            __sincosf(-TWO_PI * (float)(32 * k + l) * (1.0f / 128.0f), &sn, &c);
            const float dr = zr[k] - zr[k + 2];
            const float di = zi[k] - zi[k + 2];
            zr[k] += zr[k + 2];
            zi[k] += zi[k + 2];
            zr[k + 2] = fmaf(dr, c,  -di * sn);
            zi[k + 2] = fmaf(dr, sn,  di * c);
        }
        // H=32: pairs (0,1) and (2,3), angle = -2*pi*l/64 (same for both)
        float sn, c;
        __sincosf(-TWO_PI * (float)l * (1.0f / 64.0f), &sn, &c);
#pragma unroll
        for (int k = 0; k < 4; k += 2) {
            const float dr = zr[k] - zr[k + 1];
            const float di = zi[k] - zi[k + 1];
            zr[k] += zr[k + 1];
            zi[k] += zi[k + 1];
            zr[k + 1] = fmaf(dr, c,  -di * sn);
            zi[k + 1] = fmaf(dr, sn,  di * c);
        }
    }

    // ---- Shfl stages H=16..1 on each register ----
#pragma unroll
    for (int h = 16; h >= 1; h >>= 1) {
        const int step = 16 / h;
        float twn, twc;
        __sincosf(-TWO_PI * (float)(step * (l & (h - 1))) * (1.0f / 32.0f),
                  &twn, &twc);
        const bool bot = (l & h) != 0;
#pragma unroll
        for (int k = 0; k < 4; ++k) {
            const float pr = __shfl_xor_sync(0xffffffffu, zr[k], h);
            const float pi = __shfl_xor_sync(0xffffffffu, zi[k], h);
            const float dr = pr - zr[k];
            const float di = pi - zi[k];
            const float tr = fmaf(dr, twc, -di * twn);
            const float ti = fmaf(dr, twn,  di * twc);
            zr[k] = bot ? tr : (zr[k] + pr);
            zi[k] = bot ? ti : (zi[k] + pi);
        }
    }

    // ---- Emit: f = 16*bitrev5(l) + bitrev4(4m+k) ----
    const int q5 = ((l & 1) << 4) | ((l & 2) << 2) | (l & 4)
                 | ((l & 8) >> 2) | ((l & 16) >> 4);          // bitrev5(l)
    const int brm = ((m & 1) << 1) | (m >> 1);                // bitrev2(m)

    if ((l & 1) == 0) {                                       // q5 <= 15
        const int fbase = (q5 << 4) | brm;
        const int brk[4] = {0, 8, 4, 12};                     // bitrev2(k) << 2
#pragma unroll
        for (int k = 0; k < 4; ++k) {
            const int f = fbase | brk[k];
            float sp, cp;
            __sincosf(TWO_PI * frac * (float)f * (1.0f / 512.0f), &sp, &cp);
            const float re = fmaf(zr[k], cp, -zi[k] * sp);
            const float im = fmaf(zr[k], sp,  zi[k] * cp);
            const size_t o = ((size_t)b * NF + f) * NT + t;
            out[o]       = sqrtf(fmaf(re, re, im * im)) + 1.1920929e-7f;
            out[BFT + o] = re;
        }
    } else if (l == 1 && m == 0) {                            // f = 256 (kk=0)
        float sp, cp;
        __sincosf(TWO_PI * frac * 0.5f, &sp, &cp);
        const float re = fmaf(zr[0], cp, -zi[0] * sp);
        const float im = fmaf(zr[0], sp,  zi[0] * cp);
        const size_t o = ((size_t)b * NF + 256) * NT + t;
        out[o]       = sqrtf(fmaf(re, re, im * im)) + 1.1920929e-7f;
        out[BFT + o] = re;
    }
}

// ---------------------------------------------------------------------------
extern "C" void kernel_launch(void* const* d_in, const int* in_sizes, int n_in,
                              void* d_out, int out_size) {
    // x is the unique large input; win_length is the middle input under both
    // insertion and alphabetical order; strides is the remaining small one.
    int ix = 0;
    for (int i = 1; i < n_in; ++i)
        if (in_sizes[i] > in_sizes[ix]) ix = i;
    const float* x  = (const float*)d_in[ix];
    const float* wl = (const float*)d_in[1];
    const float* st = (const float*)d_in[(ix == 0) ? 2 : 0];
    float* out = (float*)d_out;

    dim3 grid(NT, NB);
    adstft_kernel<<<grid, 128>>>(x, wl, st, out);
}

// round 11
// speedup vs baseline: 1.2208x; 1.0078x over previous
#include <cuda_runtime.h>

// Fixed problem shapes: B=4, L=80000, N=512, F=257, STRIDE=256 -> T=311
#define NB  4
#define NL  80000
#define NN  512
#define NF  257
#define NT  311
#define BFT (NB * NF * NT)   // 319708

#define TWO_PI 6.2831853071795864769f

// ---------------------------------------------------------------------------
// Block = 128 threads (4 warps) per (frame t, batch b); grid (NT, NB).
// Lane l of warp m owns registers k=0..3 holding point n = 32*(4m+k) + l.
//  Cross-warp stages H=256 & H=128: fused radix-4 exchange via smem, ONE
//    barrier (verified round 10).
//  Stages H=64, 32: register-local DIF butterflies.
//  Stages H=16..1: shfl-xor butterflies (verified rounds 8-10).
//  Emit (rebalanced): even lane keeps k=0 (f=fbase|0) and k=2 (f=fbase|4);
//    k=1 (|8) and k=3 (|12) are shuffled to the odd neighbor, so every lane
//    emits exactly 2 outputs. Lane 1 of warp 0 additionally emits f=256.
// Output layout: floats [0,BFT) = spec; [BFT,2*BFT) = real(stft).
// ---------------------------------------------------------------------------
__global__ void __launch_bounds__(128, 12)
adstft_kernel(const float* __restrict__ x,
              const float* __restrict__ wlp,
              const float* __restrict__ stp,
              float* __restrict__ out) {
    __shared__ float2 sz[16][32];   // [kk][lane], 4 KB

    const int t = blockIdx.x;
    const int b = blockIdx.y;
    const int m = threadIdx.x >> 5;   // warp = quartet position
    const int l = threadIdx.x & 31;

    const float wl = fminf(fmaxf(wlp[0], 25.6f), 512.0f);   // WIN_MIN..WIN_MAX
    const float st = fminf(fmaxf(stp[0], 0.0f), 512.0f);    // STRIDE_MIN..MAX
    const float frame = st * (float)t;                       // == cumsum for integral st
    const float flo   = floorf(frame);
    const float frac  = frame - flo;
    const int   i0    = (int)flo;
    const float hi    = ceilf ((511.0f + wl) * 0.5f);
    const float lo    = floorf((511.0f - wl) * 0.5f);
    const float woff  = (wl - 511.0f) * 0.5f;

    // ---- Load + window, write to smem ----
    {
        const float* xb = x + (size_t)b * NL;
#pragma unroll
        for (int k = 0; k < 4; ++k) {
            const int n   = 32 * (4 * m + k) + l;
            const int idx = i0 + n;
            const float v = (idx >= 0 && idx < NL) ? xb[idx] : 0.0f;
            const float base = (float)n - frac;
            float tap = 0.0f;
            if (!(base >= hi || base <= lo))
                tap = (0.5f - 0.5f * __cosf(TWO_PI * (base + woff) / wl))
                      * 0.00390625f;                         // / N * 2
            sz[4 * m + k][l] = make_float2(v * tap, 0.0f);
        }
    }
    __syncthreads();

    // ---- Fused radix-4 cross-warp stages (H=256 then H=128) ----
    float zr[4], zi[4];
    {
        float wlr, wli;                               // w(l) = e^{-2*pi*i*l/512}
        __sincosf(-TWO_PI * (float)l * (1.0f / 512.0f), &wli, &wlr);
        const float KC[4] = {1.0f, 0.92387953f,  0.70710678f,  0.38268343f};
        const float KS[4] = {0.0f, -0.38268343f, -0.70710678f, -0.92387953f};
#pragma unroll
        for (int k = 0; k < 4; ++k) {
            // wA = w(l) * e^{-i*pi*k/8};  wB = wA^2
            const float wAr = wlr * KC[k] - wli * KS[k];
            const float wAi = wlr * KS[k] + wli * KC[k];
            const float wBr = wAr * wAr - wAi * wAi;
            const float wBi = 2.0f * wAr * wAi;

            const float2 c0 = sz[k     ][l];
            const float2 c1 = sz[k +  4][l];
            const float2 c2 = sz[k +  8][l];
            const float2 c3 = sz[k + 12][l];
            const float s0r = c0.x + c2.x, s0i = c0.y + c2.y;
            const float s1r = c1.x + c3.x, s1i = c1.y + c3.y;
            const float d0r = c0.x - c2.x, d0i = c0.y - c2.y;
            const float d1r = c1.x - c3.x, d1i = c1.y - c3.y;

            float rr, ri;
            if (m == 0) {                       // B0 = s0 + s1
                rr = s0r + s1r; ri = s0i + s1i;
            } else if (m == 1) {                // B1 = (s0 - s1) * wB
                const float er = s0r - s1r, ei = s0i - s1i;
                rr = er * wBr - ei * wBi;
                ri = er * wBi + ei * wBr;
            } else if (m == 2) {                // B2 = wA * (d0 - i*d1)
                const float er = d0r + d1i, ei = d0i - d1r;
                rr = er * wAr - ei * wAi;
                ri = er * wAi + ei * wAr;
            } else {                            // B3 = wA*wB * (d0 + i*d1)
                const float wCr = wAr * wBr - wAi * wBi;
                const float wCi = wAr * wBi + wAi * wBr;
                const float er = d0r - d1i, ei = d0i + d1r;
                rr = er * wCr - ei * wCi;
                ri = er * wCi + ei * wCr;
            }
            zr[k] = rr; zi[k] = ri;
        }
    }

    // ---- Register-local stages H=64 (dist 2), H=32 (dist 1) ----
    {
#pragma unroll
        for (int k = 0; k < 2; ++k) {
            float sn, c;
            __sincosf(-TWO_PI * (float)(32 * k + l) * (1.0f / 128.0f), &sn, &c);
            const float dr = zr[k] - zr[k + 2];
            const float di = zi[k] - zi[k + 2];
            zr[k] += zr[k + 2];
            zi[k] += zi[k + 2];
            zr[k + 2] = fmaf(dr, c,  -di * sn);
            zi[k + 2] = fmaf(dr, sn,  di * c);
        }
        float sn, c;
        __sincosf(-TWO_PI * (float)l * (1.0f / 64.0f), &sn, &c);
#pragma unroll
        for (int k = 0; k < 4; k += 2) {
            const float dr = zr[k] - zr[k + 1];
            const float di = zi[k] - zi[k + 1];
            zr[k] += zr[k + 1];
            zi[k] += zi[k + 1];
            zr[k + 1] = fmaf(dr, c,  -di * sn);
            zi[k + 1] = fmaf(dr, sn,  di * c);
        }
    }

    // ---- Shfl stages H=16..1 on each register ----
#pragma unroll
    for (int h = 16; h >= 1; h >>= 1) {
        const int step = 16 / h;
        float twn, twc;
        __sincosf(-TWO_PI * (float)(step * (l & (h - 1))) * (1.0f / 32.0f),
                  &twn, &twc);
        const bool bot = (l & h) != 0;
#pragma unroll
        for (int k = 0; k < 4; ++k) {
            const float pr = __shfl_xor_sync(0xffffffffu, zr[k], h);
            const float pi = __shfl_xor_sync(0xffffffffu, zi[k], h);
            const float dr = pr - zr[k];
            const float di = pi - zi[k];
            const float tr = fmaf(dr, twc, -di * twn);
            const float ti = fmaf(dr, twn,  di * twc);
            zr[k] = bot ? tr : (zr[k] + pr);
            zi[k] = bot ? ti : (zi[k] + pi);
        }
    }

    // ---- Rebalanced emit: every lane outputs 2 frequencies ----
    // Position (l, kk=4m+k) holds f = 16*bitrev5(l) + bitrev4(kk)
    //   = (bitrev5(l) << 4) | bitrev2(m) | (bitrev2(k) << 2).
    // bitrev2(k)<<2 over k=0..3 -> {0, 8, 4, 12}.
    const int q5 = ((l & 1) << 4) | ((l & 2) << 2) | (l & 4)
                 | ((l & 8) >> 2) | ((l & 16) >> 4);          // bitrev5(l)
    const int brm = ((m & 1) << 1) | (m >> 1);                // bitrev2(m)

    // Hand k=1 and k=3 results to the odd neighbor lane.
    const float pr1 = __shfl_xor_sync(0xffffffffu, zr[1], 1);
    const float pi1 = __shfl_xor_sync(0xffffffffu, zi[1], 1);
    const float pr3 = __shfl_xor_sync(0xffffffffu, zr[3], 1);
    const float pi3 = __shfl_xor_sync(0xffffffffu, zi[3], 1);

    int f0, f1;
    float e0r, e0i, e1r, e1i;
    if ((l & 1) == 0) {            // q5 <= 15: own k=0 and k=2
        const int fbase = (q5 << 4) | brm;
        f0 = fbase;      e0r = zr[0]; e0i = zi[0];
        f1 = fbase | 4;  e1r = zr[2]; e1i = zi[2];
    } else {                       // partner fbase: bitrev5(l-1) = q5 - 16
        const int fbase = ((q5 - 16) << 4) | brm;
        f0 = fbase | 8;  e0r = pr1; e0i = pi1;
        f1 = fbase | 12; e1r = pr3; e1i = pi3;
    }

    {
        float sp, cp;
        __sincosf(TWO_PI * frac * (float)f0 * (1.0f / 512.0f), &sp, &cp);
        const float re = fmaf(e0r, cp, -e0i * sp);
        const float im = fmaf(e0r, sp,  e0i * cp);
        const size_t o = ((size_t)b * NF + f0) * NT + t;
        out[o]       = sqrtf(fmaf(re, re, im * im)) + 1.1920929e-7f;
        out[BFT + o] = re;
    }
    {
        float sp, cp;
        __sincosf(TWO_PI * frac * (float)f1 * (1.0f / 512.0f), &sp, &cp);
        const float re = fmaf(e1r, cp, -e1i * sp);
        const float im = fmaf(e1r, sp,  e1i * cp);
        const size_t o = ((size_t)b * NF + f1) * NT + t;
        out[o]       = sqrtf(fmaf(re, re, im * im)) + 1.1920929e-7f;
        out[BFT + o] = re;
    }

    if (l == 1 && m == 0) {        // f = 256 from own (q5=16, kk=0) slot
        float sp, cp;
        __sincosf(TWO_PI * frac * 0.5f, &sp, &cp);
        const float re = fmaf(zr[0], cp, -zi[0] * sp);
        const float im = fmaf(zr[0], sp,  zi[0] * cp);
        const size_t o = ((size_t)b * NF + 256) * NT + t;
        out[o]       = sqrtf(fmaf(re, re, im * im)) + 1.1920929e-7f;
        out[BFT + o] = re;
    }
}

// ---------------------------------------------------------------------------
extern "C" void kernel_launch(void* const* d_in, const int* in_sizes, int n_in,
                              void* d_out, int out_size) {
    // x is the unique large input; win_length is the middle input under both
    // insertion and alphabetical order; strides is the remaining small one.
    int ix = 0;
    for (int i = 1; i < n_in; ++i)
        if (in_sizes[i] > in_sizes[ix]) ix = i;
    const float* x  = (const float*)d_in[ix];
    const float* wl = (const float*)d_in[1];
    const float* st = (const float*)d_in[(ix == 0) ? 2 : 0];
    float* out = (float*)d_out;

    dim3 grid(NT, NB);
    adstft_kernel<<<grid, 128>>>(x, wl, st, out);
}